// round 11
// baseline (speedup 1.0000x reference)
#include <cuda_runtime.h>
#include <cuda_fp16.h>
#include <cstdint>
#include <cstddef>

#define NTOK   98
#define CSTR   108
#define HEADS  4
#define DIM    128
#define BATCH  4096
#define NW     64
#define SCALE  0.17677669529663687f

__device__ unsigned g_qb[(size_t)BATCH * HEADS * NTOK * 16];  // f16x2 packed, q*SCALE
__device__ unsigned g_kb[(size_t)BATCH * HEADS * NTOK * 16];  // f16x2 packed
__device__ __half   g_vh[(size_t)BATCH * HEADS * 32 * 112];   // V transposed [dim][tok], pads 0
__device__ float    g_o [(size_t)BATCH * NTOK * DIM];
__device__ float    g_comb[(size_t)NW * HEADS * NTOK * CSTR];
__device__ float    g_qkv_wr[384 * 128];
__device__ unsigned g_qkv_wh[256 * 64];                       // q,k weights fp16x2
__device__ float    g_proj_wr[128 * 128];

__device__ __forceinline__ float tf32r(float x) {
    unsigned u;
    asm("cvt.rna.tf32.f32 %0, %1;" : "=r"(u) : "f"(x));
    return __uint_as_float(u);
}
__device__ __forceinline__ float ex2f(float x) {
    float y;
    asm("ex2.approx.f32 %0, %1;" : "=f"(y) : "f"(x));
    return y;
}
__device__ __forceinline__ unsigned h2pack(float lo, float hi) {
    unsigned u;
    asm("cvt.rn.f16x2.f32 %0, %1, %2;" : "=r"(u) : "f"(hi), "f"(lo));
    return u;
}
__device__ __forceinline__ void mma8(float c[4], float a0, float a1, float a2, float a3,
                                     float b0, float b1) {
    asm volatile(
        "mma.sync.aligned.m16n8k8.row.col.f32.tf32.tf32.f32 "
        "{%0,%1,%2,%3},{%4,%5,%6,%7},{%8,%9},{%0,%1,%2,%3};\n"
        : "+f"(c[0]), "+f"(c[1]), "+f"(c[2]), "+f"(c[3])
        : "r"(__float_as_uint(a0)), "r"(__float_as_uint(a1)),
          "r"(__float_as_uint(a2)), "r"(__float_as_uint(a3)),
          "r"(__float_as_uint(b0)), "r"(__float_as_uint(b1)));
}
__device__ __forceinline__ void mma16h(float c[4], unsigned a0, unsigned a1,
                                       unsigned a2, unsigned a3,
                                       unsigned b0, unsigned b1) {
    asm volatile(
        "mma.sync.aligned.m16n8k16.row.col.f32.f16.f16.f32 "
        "{%0,%1,%2,%3},{%4,%5,%6,%7},{%8,%9},{%0,%1,%2,%3};\n"
        : "+f"(c[0]), "+f"(c[1]), "+f"(c[2]), "+f"(c[3])
        : "r"(a0), "r"(a1), "r"(a2), "r"(a3), "r"(b0), "r"(b1));
}
__device__ __forceinline__ void cp16(void* sptr, const void* gptr) {
    unsigned s = (unsigned)__cvta_generic_to_shared(sptr);
    asm volatile("cp.async.cg.shared.global [%0], [%1], 16;\n" :: "r"(s), "l"(gptr));
}
#define CP_COMMIT() asm volatile("cp.async.commit_group;\n" ::: "memory")
#define CP_WAIT0()  asm volatile("cp.async.wait_group 0;\n" ::: "memory")
#define CP_WAIT1()  asm volatile("cp.async.wait_group 1;\n" ::: "memory")

// ---------------- K-1: pre-round weights (tf32 + fp16 for q,k rows) ----------------
__global__ void k_prep(const float* __restrict__ qkv_w, const float* __restrict__ proj_w) {
    int i = blockIdx.x * 256 + threadIdx.x;
    if (i < 384 * 128) g_qkv_wr[i] = tf32r(qkv_w[i]);
    if (i < 128 * 128) g_proj_wr[i] = tf32r(proj_w[i]);
    if (i < 256 * 64) {
        int r = i >> 6, j = i & 63;
        g_qkv_wh[i] = h2pack(qkv_w[r * 128 + 2 * j], qkv_w[r * 128 + 2 * j + 1]);
    }
}

// ---------------- K0: comb = mask + gathered bias, padded ----------------
__global__ void k_comb(const float* __restrict__ mask,
                       const float* __restrict__ rpb,
                       const int* __restrict__ relidx) {
    const int w = blockIdx.x >> 2, h = blockIdx.x & 3;
    float* dst = g_comb + (size_t)(w * HEADS + h) * NTOK * CSTR;
    const float* msk = mask + (size_t)w * NTOK * NTOK;
    for (int idx = threadIdx.x; idx < NTOK * CSTR; idx += blockDim.x) {
        int i = idx / CSTR, j = idx - i * CSTR;
        float v = -10000.0f;
        if (j < NTOK) v = msk[i * NTOK + j] + rpb[relidx[i * NTOK + j] * HEADS + h];
        dst[idx] = v;
    }
}

// ---------------- K1a: V GEMM (tf32), weight rows 256..383 ----------------
#define QKVV_SMEM_BYTES ((128 * 132 + 2 * 128 * 36) * 4)

__global__ void __launch_bounds__(256, 2) k_qkv_v(const float* __restrict__ x,
                                                  const float* __restrict__ bias) {
    extern __shared__ float smq[];
    float (*As)[132] = reinterpret_cast<float(*)[132]>(smq);
    float* Bsbuf = smq + 128 * 132;                 // 2 x [128][36]
    const int m0 = blockIdx.x * 128;
    const int tid = threadIdx.x, lane = tid & 31, warp = tid >> 5;
    const int g = lane >> 2, tg = lane & 3;
    const int wm = warp >> 2, wn = warp & 3;
    const int fi = (tid & 7) * 4, r0 = tid >> 3;

    {   // load full 128x128 x tile once (rna-rounded)
        const int c = (tid & 31) * 4, rb = tid >> 5;
#pragma unroll
        for (int rr = 0; rr < 16; rr++) {
            int r = rb + rr * 8;
            float4 v4 = *reinterpret_cast<const float4*>(&x[(size_t)(m0 + r) * 128 + c]);
            *reinterpret_cast<float4*>(&As[r][c]) =
                make_float4(tf32r(v4.x), tf32r(v4.y), tf32r(v4.z), tf32r(v4.w));
        }
    }

    auto prefetchB = [&](int c, int buf) {
        const float* src = g_qkv_wr + (size_t)256 * 128 + c * 32;
        float* dst = Bsbuf + buf * (128 * 36);
#pragma unroll
        for (int rr = 0; rr < 4; rr++) {
            int r = r0 + rr * 32;
            cp16(&dst[r * 36 + fi], &src[(size_t)r * 128 + fi]);
        }
    };
    prefetchB(0, 0);
    CP_COMMIT();

    float c4[4][4][4];
#pragma unroll
    for (int i = 0; i < 4; i++)
#pragma unroll
        for (int j = 0; j < 4; j++)
#pragma unroll
            for (int q = 0; q < 4; q++) c4[i][j][q] = 0.f;

    for (int c = 0; c < 4; c++) {
        const int kk = c * 32;
        const float* Bs = Bsbuf + (c & 1) * (128 * 36);
        CP_WAIT0();
        __syncthreads();
        if (c + 1 < 4) { prefetchB(c + 1, (c + 1) & 1); CP_COMMIT(); }
#pragma unroll
        for (int ks = 0; ks < 32; ks += 8) {
            float a[4][4], bb[4][2];
#pragma unroll
            for (int mi = 0; mi < 4; mi++) {
                int rr = wm * 64 + mi * 16 + g;
                a[mi][0] = As[rr][kk + ks + tg];     a[mi][1] = As[rr + 8][kk + ks + tg];
                a[mi][2] = As[rr][kk + ks + tg + 4]; a[mi][3] = As[rr + 8][kk + ks + tg + 4];
            }
#pragma unroll
            for (int ni = 0; ni < 4; ni++) {
                int cc = wn * 32 + ni * 8 + g;
                bb[ni][0] = Bs[cc * 36 + ks + tg]; bb[ni][1] = Bs[cc * 36 + ks + tg + 4];
            }
#pragma unroll
            for (int mi = 0; mi < 4; mi++)
#pragma unroll
                for (int ni = 0; ni < 4; ni++)
                    mma8(c4[mi][ni], a[mi][0], a[mi][1], a[mi][2], a[mi][3],
                         bb[ni][0], bb[ni][1]);
        }
        __syncthreads();
    }
    // V epilogue: fp16 transposed [dim][112 tok]
#pragma unroll
    for (int ni = 0; ni < 4; ni++) {
        int col = 256 + wn * 32 + ni * 8 + tg * 2;
        float b0 = bias[col], b1 = bias[col + 1];
        int o = col & 127, h = o >> 5, d = o & 31;
#pragma unroll
        for (int mi = 0; mi < 4; mi++) {
            int m = m0 + wm * 64 + mi * 16 + g;
            int b = m / NTOK, n = m - b * NTOK;
            int m2 = m + 8, b2 = m2 / NTOK, n2 = m2 - b2 * NTOK;
            size_t bh1 = (size_t)b * HEADS + h;
            size_t bh2 = (size_t)b2 * HEADS + h;
            g_vh[(bh1 * 32 + d)     * 112 + n]  = __float2half(c4[mi][ni][0] + b0);
            g_vh[(bh1 * 32 + d + 1) * 112 + n]  = __float2half(c4[mi][ni][1] + b1);
            g_vh[(bh2 * 32 + d)     * 112 + n2] = __float2half(c4[mi][ni][2] + b0);
            g_vh[(bh2 * 32 + d + 1) * 112 + n2] = __float2half(c4[mi][ni][3] + b1);
        }
    }
}

// ---------------- K1b: Q,K GEMM (fp16) — all weights resident, single sync ----------------
#define WHU 68                                   // weight row stride (u32): 64 data + 4 pad
#define QKVQK_SMEM_BYTES ((128 * 68 + 256 * WHU) * 4)

__global__ void __launch_bounds__(256, 2) k_qkv_qk(const float* __restrict__ x,
                                                   const float* __restrict__ bias) {
    extern __shared__ unsigned smqk[];
    unsigned* As16 = smqk;                    // [128][68] f16x2 (64 data + 4 pad)
    unsigned* Wh   = smqk + 128 * 68;         // [256][68] f16x2 — ALL q,k weights
    const int m0 = blockIdx.x * 128;
    const int tid = threadIdx.x, lane = tid & 31, warp = tid >> 5;
    const int g = lane >> 2, tg = lane & 3;
    const int wm = warp >> 2, wn = warp & 3;

    // bulk cp.async: all 256x64 u32 of q,k weights (16 cp16 per thread)
#pragma unroll
    for (int ii = 0; ii < 16; ii++) {
        int i = tid + ii * 256;               // 0..4095
        int r = i >> 4, c = (i & 15) * 4;
        cp16(&Wh[r * WHU + c], &g_qkv_wh[(size_t)r * 64 + c]);
    }
    CP_COMMIT();

    {   // x tile fp32 -> f16x2 into As16 (independent of cp.async; overlaps it)
        int row = tid >> 1, half = tid & 1;
        const float* srcr = &x[(size_t)(m0 + row) * 128 + half * 64];
        unsigned* dstr = &As16[row * 68 + half * 32];
#pragma unroll
        for (int j = 0; j < 16; j++) {
            float4 v4 = *reinterpret_cast<const float4*>(&srcr[j * 4]);
            dstr[j * 2]     = h2pack(v4.x, v4.y);
            dstr[j * 2 + 1] = h2pack(v4.z, v4.w);
        }
    }
    CP_WAIT0();
    __syncthreads();                          // the only barrier

#pragma unroll
    for (int t = 0; t < 2; t++) {             // t=0: Q, t=1: K
        float c4[4][4][4];
#pragma unroll
        for (int i = 0; i < 4; i++)
#pragma unroll
            for (int j = 0; j < 4; j++)
#pragma unroll
                for (int q = 0; q < 4; q++) c4[i][j][q] = 0.f;

#pragma unroll
        for (int kc = 0; kc < 8; kc++) {      // 8 x k16 chunks, no barriers
            const int base = kc * 8;
            unsigned a[4][4], bb[4][2];
#pragma unroll
            for (int mi = 0; mi < 4; mi++) {
                int rr = wm * 64 + mi * 16 + g;
                a[mi][0] = As16[rr * 68 + base + tg];
                a[mi][1] = As16[(rr + 8) * 68 + base + tg];
                a[mi][2] = As16[rr * 68 + base + tg + 4];
                a[mi][3] = As16[(rr + 8) * 68 + base + tg + 4];
            }
#pragma unroll
            for (int ni = 0; ni < 4; ni++) {
                int cc = t * 128 + wn * 32 + ni * 8 + g;
                bb[ni][0] = Wh[cc * WHU + base + tg];
                bb[ni][1] = Wh[cc * WHU + base + tg + 4];
            }
#pragma unroll
            for (int mi = 0; mi < 4; mi++)
#pragma unroll
                for (int ni = 0; ni < 4; ni++)
                    mma16h(c4[mi][ni], a[mi][0], a[mi][1], a[mi][2], a[mi][3],
                           bb[ni][0], bb[ni][1]);
        }

        // epilogue: q (t=0, *SCALE) or k (t=1)
        float sc = (t == 0) ? SCALE : 1.0f;
        unsigned* basep = (t == 0) ? g_qb : g_kb;
#pragma unroll
        for (int ni = 0; ni < 4; ni++) {
            int col = t * 128 + wn * 32 + ni * 8 + tg * 2;
            float b0 = bias[col], b1 = bias[col + 1];
            int o = col & 127, h = o >> 5, d = o & 31;
#pragma unroll
            for (int mi = 0; mi < 4; mi++) {
                int m = m0 + wm * 64 + mi * 16 + g;
                int b = m / NTOK, n = m - b * NTOK;
                int m2 = m + 8, b2 = m2 / NTOK, n2 = m2 - b2 * NTOK;
                size_t bh1 = (size_t)b * HEADS + h;
                size_t bh2 = (size_t)b2 * HEADS + h;
                basep[(bh1 * NTOK + n)  * 16 + (d >> 1)] =
                    h2pack((c4[mi][ni][0] + b0) * sc, (c4[mi][ni][1] + b1) * sc);
                basep[(bh2 * NTOK + n2) * 16 + (d >> 1)] =
                    h2pack((c4[mi][ni][2] + b0) * sc, (c4[mi][ni][3] + b1) * sc);
            }
        }
    }
}

// ---------------- K2: fused attention, fp16 QK^T + fp16 PV (FA2 P-reuse) ----------------
#define KSU  20
#define VTU  60
#define SM_KU (NTOK * CSTR)
#define SM_VU (SM_KU + 104 * KSU)
#define ATTN_SMEM_BYTES ((SM_VU + 32 * VTU) * 4)
#define ATHREADS 224

__global__ void __launch_bounds__(ATHREADS, 3) k_attn() {
    extern __shared__ float sm[];
    float*    comb_s = sm;                                     // [98][108] fp32
    unsigned* k_su = reinterpret_cast<unsigned*>(sm + SM_KU);  // [104][20] f16x2
    unsigned* v_su = reinterpret_cast<unsigned*>(sm + SM_VU);  // [32][60]  f16x2 (V_t)

    const int t = blockIdx.x, h = blockIdx.y, w = blockIdx.z;
    const int tid = threadIdx.x, lane = tid & 31, warp = tid >> 5;
    const int g = lane >> 2, tg = lane & 3;
    const int r1 = warp * 16 + g, r2 = r1 + 8;
    const int cr1 = min(r1, NTOK - 1), cr2 = min(r2, NTOK - 1);
    const unsigned FULL = 0xffffffffu;
    const float L2E = 1.4426950408889634f;

    {
        const float* cg = g_comb + (size_t)(w * HEADS + h) * NTOK * CSTR;
        for (int i = tid; i < NTOK * CSTR; i += ATHREADS) comb_s[i] = cg[i];
    }
    for (int i = tid; i < 6 * KSU; i += ATHREADS) k_su[98 * KSU + i] = 0u;

    for (int jj = 0; jj < 8; jj++) {
        const int b = (t * 8 + jj) * NW + w;
        const size_t bh = (size_t)b * HEADS + h;
        const unsigned* gqb = g_qb + bh * NTOK * 16;
        const unsigned* gkb = g_kb + bh * NTOK * 16;
        const __half*   gvh = g_vh + bh * 32 * 112;

        __syncthreads();
        for (int i = tid; i < 392; i += ATHREADS) {     // K: 98 rows x 4 cp16
            int r = i >> 2, c = (i & 3) * 4;
            cp16(&k_su[r * KSU + c], &gkb[r * 16 + c]);
        }
        CP_COMMIT();
        for (int i = tid; i < 448; i += ATHREADS) {     // V_t: 32 rows x 14 cp16
            int r = i / 14, c = i - r * 14;
            cp16(&v_su[r * VTU + c * 4], &gvh[r * 112 + c * 8]);
        }
        CP_COMMIT();

        unsigned qu[2][4] = {{0u,0u,0u,0u},{0u,0u,0u,0u}};
        if (r1 < NTOK) {
            qu[0][0] = gqb[r1 * 16 + tg];     qu[0][2] = gqb[r1 * 16 + tg + 4];
            qu[1][0] = gqb[r1 * 16 + 8 + tg]; qu[1][2] = gqb[r1 * 16 + 8 + tg + 4];
        }
        if (r2 < NTOK) {
            qu[0][1] = gqb[r2 * 16 + tg];     qu[0][3] = gqb[r2 * 16 + tg + 4];
            qu[1][1] = gqb[r2 * 16 + 8 + tg]; qu[1][3] = gqb[r2 * 16 + 8 + tg + 4];
        }
        CP_WAIT1();
        __syncthreads();

        float s[13][4];
#pragma unroll
        for (int ni = 0; ni < 13; ni++)
            s[ni][0] = s[ni][1] = s[ni][2] = s[ni][3] = 0.f;
#pragma unroll
        for (int ch = 0; ch < 2; ch++) {
#pragma unroll
            for (int ni = 0; ni < 13; ni++) {
                unsigned b0 = k_su[(ni * 8 + g) * KSU + ch * 8 + tg];
                unsigned b1 = k_su[(ni * 8 + g) * KSU + ch * 8 + tg + 4];
                mma16h(s[ni], qu[ch][0], qu[ch][1], qu[ch][2], qu[ch][3], b0, b1);
            }
        }
        float m1 = -1e30f, m2 = -1e30f;
#pragma unroll
        for (int ni = 0; ni < 13; ni++) {
            int c0 = ni * 8 + tg * 2;
            float2 ca = *reinterpret_cast<const float2*>(&comb_s[cr1 * CSTR + c0]);
            float2 cb = *reinterpret_cast<const float2*>(&comb_s[cr2 * CSTR + c0]);
            s[ni][0] += ca.x; s[ni][1] += ca.y;
            s[ni][2] += cb.x; s[ni][3] += cb.y;
            m1 = fmaxf(m1, fmaxf(s[ni][0], s[ni][1]));
            m2 = fmaxf(m2, fmaxf(s[ni][2], s[ni][3]));
        }
        m1 = fmaxf(m1, __shfl_xor_sync(FULL, m1, 1));
        m1 = fmaxf(m1, __shfl_xor_sync(FULL, m1, 2));
        m2 = fmaxf(m2, __shfl_xor_sync(FULL, m2, 1));
        m2 = fmaxf(m2, __shfl_xor_sync(FULL, m2, 2));
        float sum1 = 0.f, sum2 = 0.f;
#pragma unroll
        for (int ni = 0; ni < 13; ni++) {
            s[ni][0] = ex2f((s[ni][0] - m1) * L2E);
            s[ni][1] = ex2f((s[ni][1] - m1) * L2E);
            s[ni][2] = ex2f((s[ni][2] - m2) * L2E);
            s[ni][3] = ex2f((s[ni][3] - m2) * L2E);
            sum1 += s[ni][0] + s[ni][1];
            sum2 += s[ni][2] + s[ni][3];
        }
        sum1 += __shfl_xor_sync(FULL, sum1, 1);
        sum1 += __shfl_xor_sync(FULL, sum1, 2);
        sum2 += __shfl_xor_sync(FULL, sum2, 1);
        sum2 += __shfl_xor_sync(FULL, sum2, 2);
        float inv1 = 1.0f / sum1, inv2 = 1.0f / sum2;

        CP_WAIT0();
        __syncthreads();

        float o[4][4];
#pragma unroll
        for (int ni = 0; ni < 4; ni++) o[ni][0] = o[ni][1] = o[ni][2] = o[ni][3] = 0.f;
#pragma unroll
        for (int kt = 0; kt < 7; kt++) {
            unsigned a0 = h2pack(s[2 * kt][0], s[2 * kt][1]);
            unsigned a1 = h2pack(s[2 * kt][2], s[2 * kt][3]);
            unsigned a2 = 0u, a3 = 0u;
            if (kt < 6) {
                a2 = h2pack(s[2 * kt + 1][0], s[2 * kt + 1][1]);
                a3 = h2pack(s[2 * kt + 1][2], s[2 * kt + 1][3]);
            }
#pragma unroll
            for (int ni = 0; ni < 4; ni++) {
                unsigned b0 = v_su[(ni * 8 + g) * VTU + 8 * kt + tg];
                unsigned b1 = v_su[(ni * 8 + g) * VTU + 8 * kt + tg + 4];
                mma16h(o[ni], a0, a1, a2, a3, b0, b1);
            }
        }
        float* gob = g_o + (size_t)b * NTOK * DIM + h * 32;
#pragma unroll
        for (int ni = 0; ni < 4; ni++) {
            int d = ni * 8 + tg * 2;
            if (r1 < NTOK)
                *reinterpret_cast<float2*>(&gob[r1 * DIM + d]) =
                    make_float2(tf32r(o[ni][0] * inv1), tf32r(o[ni][1] * inv1));
            if (r2 < NTOK)
                *reinterpret_cast<float2*>(&gob[r2 * DIM + d]) =
                    make_float2(tf32r(o[ni][2] * inv2), tf32r(o[ni][3] * inv2));
        }
    }
}

// ---------------- K3: output projection, 3-stage cp.async pipeline ----------------
#define PROJ_SMEM_BYTES (6 * 128 * 36 * 4)

__global__ void __launch_bounds__(256, 2) k_proj(const float* __restrict__ bias,
                                                 float* __restrict__ out) {
    extern __shared__ float smp[];
    float* Asb = smp;                   // 3 x [128][36]
    float* Bsb = smp + 3 * 128 * 36;    // 3 x [128][36]
    const int m0 = blockIdx.x * 128;
    const int tid = threadIdx.x, lane = tid & 31, warp = tid >> 5;
    const int g = lane >> 2, tg = lane & 3;
    const int wm = warp >> 2, wn = warp & 3;
    const int fi = (tid & 7) * 4, r0 = tid >> 3;

    auto prefetch = [&](int c, int buf) {
        const int kk = c * 32;
        float* ad = Asb + buf * (128 * 36);
        float* bd = Bsb + buf * (128 * 36);
#pragma unroll
        for (int rr = 0; rr < 4; rr++) {
            int r = r0 + rr * 32;
            cp16(&ad[r * 36 + fi], &g_o[(size_t)(m0 + r) * 128 + kk + fi]);
            cp16(&bd[r * 36 + fi], &g_proj_wr[(size_t)r * 128 + kk + fi]);
        }
    };
    prefetch(0, 0); CP_COMMIT();
    prefetch(1, 1); CP_COMMIT();

    float c4[4][4][4];
#pragma unroll
    for (int i = 0; i < 4; i++)
#pragma unroll
        for (int j = 0; j < 4; j++)
#pragma unroll
            for (int q = 0; q < 4; q++) c4[i][j][q] = 0.f;

    for (int c = 0; c < 4; c++) {
        const int buf = c % 3;
        const float* As = Asb + buf * (128 * 36);
        const float* Bs = Bsb + buf * (128 * 36);
        CP_WAIT1();
        __syncthreads();
        if (c + 2 < 4) { prefetch(c + 2, (c + 2) % 3); CP_COMMIT(); }
#pragma unroll
        for (int ks = 0; ks < 32; ks += 8) {
            float a[4][4], bb[4][2];
#pragma unroll
            for (int mi = 0; mi < 4; mi++) {
                int rr = wm * 64 + mi * 16 + g;
                a[mi][0] = As[rr * 36 + ks + tg];     a[mi][1] = As[(rr + 8) * 36 + ks + tg];
                a[mi][2] = As[rr * 36 + ks + tg + 4]; a[mi][3] = As[(rr + 8) * 36 + ks + tg + 4];
            }
#pragma unroll
            for (int ni = 0; ni < 4; ni++) {
                int cc = wn * 32 + ni * 8 + g;
                bb[ni][0] = Bs[cc * 36 + ks + tg]; bb[ni][1] = Bs[cc * 36 + ks + tg + 4];
            }
#pragma unroll
            for (int mi = 0; mi < 4; mi++)
#pragma unroll
                for (int ni = 0; ni < 4; ni++)
                    mma8(c4[mi][ni], a[mi][0], a[mi][1], a[mi][2], a[mi][3],
                         bb[ni][0], bb[ni][1]);
        }
        __syncthreads();
    }
#pragma unroll
    for (int ni = 0; ni < 4; ni++) {
        int col = wn * 32 + ni * 8 + tg * 2;
        float b0 = bias[col], b1 = bias[col + 1];
#pragma unroll
        for (int mi = 0; mi < 4; mi++) {
            int m = m0 + wm * 64 + mi * 16 + g;
            *reinterpret_cast<float2*>(&out[(size_t)m * 128 + col]) =
                make_float2(c4[mi][ni][0] + b0, c4[mi][ni][1] + b1);
            *reinterpret_cast<float2*>(&out[(size_t)(m + 8) * 128 + col]) =
                make_float2(c4[mi][ni][2] + b0, c4[mi][ni][3] + b1);
        }
    }
}

extern "C" void kernel_launch(void* const* d_in, const int* in_sizes, int n_in,
                              void* d_out, int out_size) {
    const float* x      = (const float*)d_in[0];
    const float* mask   = (const float*)d_in[1];
    const float* rpb    = (const float*)d_in[2];
    const float* qkv_w  = (const float*)d_in[3];
    const float* qkv_b  = (const float*)d_in[4];
    const float* proj_w = (const float*)d_in[5];
    const float* proj_b = (const float*)d_in[6];
    const int*   relidx = (const int*)d_in[7];
    float* out = (float*)d_out;

    cudaFuncSetAttribute(k_qkv_v,  cudaFuncAttributeMaxDynamicSharedMemorySize, QKVV_SMEM_BYTES);
    cudaFuncSetAttribute(k_qkv_qk, cudaFuncAttributeMaxDynamicSharedMemorySize, QKVQK_SMEM_BYTES);
    cudaFuncSetAttribute(k_attn,   cudaFuncAttributeMaxDynamicSharedMemorySize, ATTN_SMEM_BYTES);
    cudaFuncSetAttribute(k_proj,   cudaFuncAttributeMaxDynamicSharedMemorySize, PROJ_SMEM_BYTES);

    k_prep<<<192, 256>>>(qkv_w, proj_w);
    k_comb<<<NW * HEADS, 256>>>(mask, rpb, relidx);
    k_qkv_v<<<BATCH * NTOK / 128, 256, QKVV_SMEM_BYTES>>>(x, qkv_b);
    k_qkv_qk<<<BATCH * NTOK / 128, 256, QKVQK_SMEM_BYTES>>>(x, qkv_b);
    k_attn<<<dim3(8, HEADS, NW), ATHREADS, ATTN_SMEM_BYTES>>>();
    k_proj<<<BATCH * NTOK / 128, 256, PROJ_SMEM_BYTES>>>(proj_b, out);
}

// round 12
// speedup vs baseline: 1.1735x; 1.1735x over previous
#include <cuda_runtime.h>
#include <cuda_fp16.h>
#include <cstdint>
#include <cstddef>

#define NTOK   98
#define CSTR   108
#define HEADS  4
#define DIM    128
#define BATCH  4096
#define NW     64
#define SCALE  0.17677669529663687f

__device__ unsigned g_qb[(size_t)BATCH * HEADS * NTOK * 16];  // f16x2 packed, q*SCALE
__device__ unsigned g_kb[(size_t)BATCH * HEADS * NTOK * 16];  // f16x2 packed
__device__ __half   g_vh[(size_t)BATCH * HEADS * 32 * 112];   // V transposed [dim][tok], pads 0
__device__ float    g_o [(size_t)BATCH * NTOK * DIM];
__device__ float    g_comb[(size_t)NW * HEADS * NTOK * CSTR];
__device__ float    g_qkv_wr[384 * 128];                      // tf32-rounded (V rows used)
__device__ unsigned g_qkv_wh[256 * 64];                       // q,k weights fp16x2
__device__ float    g_proj_wr[128 * 128];

__device__ __forceinline__ float tf32r(float x) {
    unsigned u;
    asm("cvt.rna.tf32.f32 %0, %1;" : "=r"(u) : "f"(x));
    return __uint_as_float(u);
}
__device__ __forceinline__ float ex2f(float x) {
    float y;
    asm("ex2.approx.f32 %0, %1;" : "=f"(y) : "f"(x));
    return y;
}
__device__ __forceinline__ unsigned h2pack(float lo, float hi) {
    unsigned u;
    asm("cvt.rn.f16x2.f32 %0, %1, %2;" : "=r"(u) : "f"(hi), "f"(lo));
    return u;
}
__device__ __forceinline__ void mma8(float c[4], float a0, float a1, float a2, float a3,
                                     float b0, float b1) {
    asm volatile(
        "mma.sync.aligned.m16n8k8.row.col.f32.tf32.tf32.f32 "
        "{%0,%1,%2,%3},{%4,%5,%6,%7},{%8,%9},{%0,%1,%2,%3};\n"
        : "+f"(c[0]), "+f"(c[1]), "+f"(c[2]), "+f"(c[3])
        : "r"(__float_as_uint(a0)), "r"(__float_as_uint(a1)),
          "r"(__float_as_uint(a2)), "r"(__float_as_uint(a3)),
          "r"(__float_as_uint(b0)), "r"(__float_as_uint(b1)));
}
__device__ __forceinline__ void mma16h(float c[4], unsigned a0, unsigned a1,
                                       unsigned a2, unsigned a3,
                                       unsigned b0, unsigned b1) {
    asm volatile(
        "mma.sync.aligned.m16n8k16.row.col.f32.f16.f16.f32 "
        "{%0,%1,%2,%3},{%4,%5,%6,%7},{%8,%9},{%0,%1,%2,%3};\n"
        : "+f"(c[0]), "+f"(c[1]), "+f"(c[2]), "+f"(c[3])
        : "r"(a0), "r"(a1), "r"(a2), "r"(a3), "r"(b0), "r"(b1));
}
__device__ __forceinline__ void cp16(void* sptr, const void* gptr) {
    unsigned s = (unsigned)__cvta_generic_to_shared(sptr);
    asm volatile("cp.async.cg.shared.global [%0], [%1], 16;\n" :: "r"(s), "l"(gptr));
}
#define CP_COMMIT() asm volatile("cp.async.commit_group;\n" ::: "memory")
#define CP_WAIT0()  asm volatile("cp.async.wait_group 0;\n" ::: "memory")
#define CP_WAIT1()  asm volatile("cp.async.wait_group 1;\n" ::: "memory")

// ---------------- K-1: pre-round weights (tf32 + fp16 for q,k rows) ----------------
__global__ void k_prep(const float* __restrict__ qkv_w, const float* __restrict__ proj_w) {
    int i = blockIdx.x * 256 + threadIdx.x;
    if (i < 384 * 128) g_qkv_wr[i] = tf32r(qkv_w[i]);
    if (i < 128 * 128) g_proj_wr[i] = tf32r(proj_w[i]);
    if (i < 256 * 64) {
        int r = i >> 6, j = i & 63;
        g_qkv_wh[i] = h2pack(qkv_w[r * 128 + 2 * j], qkv_w[r * 128 + 2 * j + 1]);
    }
}

// ---------------- K0: comb = mask + gathered bias, padded ----------------
__global__ void k_comb(const float* __restrict__ mask,
                       const float* __restrict__ rpb,
                       const int* __restrict__ relidx) {
    const int w = blockIdx.x >> 2, h = blockIdx.x & 3;
    float* dst = g_comb + (size_t)(w * HEADS + h) * NTOK * CSTR;
    const float* msk = mask + (size_t)w * NTOK * NTOK;
    for (int idx = threadIdx.x; idx < NTOK * CSTR; idx += blockDim.x) {
        int i = idx / CSTR, j = idx - i * CSTR;
        float v = -10000.0f;
        if (j < NTOK) v = msk[i * NTOK + j] + rpb[relidx[i * NTOK + j] * HEADS + h];
        dst[idx] = v;
    }
}

// ---------------- K1: merged QKV — Q,K chunks fp16, V chunks tf32 (R8 skeleton) --------
#define QKV_SMEM_BYTES ((128 * 132 + 2 * 128 * 36) * 4)

__global__ void __launch_bounds__(256, 2) k_qkv(const float* __restrict__ x,
                                                const float* __restrict__ bias) {
    extern __shared__ float smq[];
    float (*As)[132] = reinterpret_cast<float(*)[132]>(smq);   // fp32 x tile, whole kernel
    float* Bsbuf = smq + 128 * 132;                             // 2 x 18432B chunk buffers
    const int m0 = blockIdx.x * 128;
    const int tid = threadIdx.x, lane = tid & 31, warp = tid >> 5;
    const int g = lane >> 2, tg = lane & 3;
    const int wm = warp >> 2, wn = warp & 3;
    const int fi = (tid & 7) * 4, r0 = tid >> 3;

    {   // load full 128x128 x tile once (rna-rounded)
        const int c = (tid & 31) * 4, rb = tid >> 5;
#pragma unroll
        for (int rr = 0; rr < 16; rr++) {
            int r = rb + rr * 8;
            float4 v4 = *reinterpret_cast<const float4*>(&x[(size_t)(m0 + r) * 128 + c]);
            *reinterpret_cast<float4*>(&As[r][c]) =
                make_float4(tf32r(v4.x), tf32r(v4.y), tf32r(v4.z), tf32r(v4.w));
        }
    }

    // chunk c: 0..7 = Q,K fp16 (t=c>>2, kk32=c&3); 8..11 = V tf32 (kk32=c-8)
    auto prefetch = [&](int c, int buf) {
        if (c < 8) {    // fp16 weights: 128 rows x 16 u32, stride 20
            const unsigned* src = g_qkv_wh + (size_t)((c >> 2) * 128) * 64 + (c & 3) * 16;
            unsigned* dst = reinterpret_cast<unsigned*>(Bsbuf + buf * (128 * 36));
#pragma unroll
            for (int ii = 0; ii < 2; ii++) {
                int i = tid + ii * 256;           // 0..511
                int r = i >> 2, q4 = (i & 3) * 4;
                cp16(&dst[r * 20 + q4], &src[(size_t)r * 64 + q4]);
            }
        } else {        // fp32 V weights: 128 rows x 32 floats, stride 36
            const float* src = g_qkv_wr + (size_t)256 * 128 + (c - 8) * 32;
            float* dst = Bsbuf + buf * (128 * 36);
#pragma unroll
            for (int rr = 0; rr < 4; rr++) {
                int r = r0 + rr * 32;
                cp16(&dst[r * 36 + fi], &src[(size_t)r * 128 + fi]);
            }
        }
    };
    prefetch(0, 0);
    CP_COMMIT();

    float c4[4][4][4];
    for (int c = 0; c < 12; c++) {
        const int kk = (c & 3) * 32;
        if ((c & 3) == 0) {
#pragma unroll
            for (int i = 0; i < 4; i++)
#pragma unroll
                for (int j = 0; j < 4; j++)
#pragma unroll
                    for (int q = 0; q < 4; q++) c4[i][j][q] = 0.f;
        }
        CP_WAIT0();
        __syncthreads();
        if (c + 1 < 12) { prefetch(c + 1, (c + 1) & 1); CP_COMMIT(); }

        if (c < 8) {    // fp16 k32 chunk = 2 x m16n8k16
            const unsigned* Bh = reinterpret_cast<const unsigned*>(Bsbuf + (c & 1) * (128 * 36));
            const int kkv = (c & 3) * 32;
#pragma unroll
            for (int ks = 0; ks < 2; ks++) {
                const int base = kkv + ks * 16;
                unsigned a[4][4], bb[4][2];
#pragma unroll
                for (int mi = 0; mi < 4; mi++) {
                    int rr = wm * 64 + mi * 16 + g;
                    float2 lo1 = *reinterpret_cast<const float2*>(&As[rr][base + 2 * tg]);
                    float2 lo2 = *reinterpret_cast<const float2*>(&As[rr + 8][base + 2 * tg]);
                    float2 hi1 = *reinterpret_cast<const float2*>(&As[rr][base + 8 + 2 * tg]);
                    float2 hi2 = *reinterpret_cast<const float2*>(&As[rr + 8][base + 8 + 2 * tg]);
                    a[mi][0] = h2pack(lo1.x, lo1.y);
                    a[mi][1] = h2pack(lo2.x, lo2.y);
                    a[mi][2] = h2pack(hi1.x, hi1.y);
                    a[mi][3] = h2pack(hi2.x, hi2.y);
                }
#pragma unroll
                for (int ni = 0; ni < 4; ni++) {
                    int cc = wn * 32 + ni * 8 + g;
                    bb[ni][0] = Bh[cc * 20 + ks * 8 + tg];
                    bb[ni][1] = Bh[cc * 20 + ks * 8 + tg + 4];
                }
#pragma unroll
                for (int mi = 0; mi < 4; mi++)
#pragma unroll
                    for (int ni = 0; ni < 4; ni++)
                        mma16h(c4[mi][ni], a[mi][0], a[mi][1], a[mi][2], a[mi][3],
                               bb[ni][0], bb[ni][1]);
            }
        } else {        // tf32 k32 chunk = 4 x m16n8k8 (V)
            const float* Bs = Bsbuf + (c & 1) * (128 * 36);
#pragma unroll
            for (int ks = 0; ks < 32; ks += 8) {
                float a[4][4], bb[4][2];
#pragma unroll
                for (int mi = 0; mi < 4; mi++) {
                    int rr = wm * 64 + mi * 16 + g;
                    a[mi][0] = As[rr][kk + ks + tg];     a[mi][1] = As[rr + 8][kk + ks + tg];
                    a[mi][2] = As[rr][kk + ks + tg + 4]; a[mi][3] = As[rr + 8][kk + ks + tg + 4];
                }
#pragma unroll
                for (int ni = 0; ni < 4; ni++) {
                    int cc = wn * 32 + ni * 8 + g;
                    bb[ni][0] = Bs[cc * 36 + ks + tg]; bb[ni][1] = Bs[cc * 36 + ks + tg + 4];
                }
#pragma unroll
                for (int mi = 0; mi < 4; mi++)
#pragma unroll
                    for (int ni = 0; ni < 4; ni++)
                        mma8(c4[mi][ni], a[mi][0], a[mi][1], a[mi][2], a[mi][3],
                             bb[ni][0], bb[ni][1]);
            }
        }
        __syncthreads();

        if ((c & 3) == 3) {   // epilogue for tile (c>>2): 0=Q, 1=K, 2=V
            int sel = c >> 2;
#pragma unroll
            for (int ni = 0; ni < 4; ni++) {
                int col = sel * 128 + wn * 32 + ni * 8 + tg * 2;
                float b0 = bias[col], b1 = bias[col + 1];
                int o = col & 127, h = o >> 5, d = o & 31;
#pragma unroll
                for (int mi = 0; mi < 4; mi++) {
                    int m = m0 + wm * 64 + mi * 16 + g;
                    int b = m / NTOK, n = m - b * NTOK;
                    int m2 = m + 8, b2 = m2 / NTOK, n2 = m2 - b2 * NTOK;
                    size_t bh1 = (size_t)b * HEADS + h;
                    size_t bh2 = (size_t)b2 * HEADS + h;
                    if (sel == 2) {   // V: fp16 transposed [dim][112 tok]
                        g_vh[(bh1 * 32 + d)     * 112 + n]  = __float2half(c4[mi][ni][0] + b0);
                        g_vh[(bh1 * 32 + d + 1) * 112 + n]  = __float2half(c4[mi][ni][1] + b1);
                        g_vh[(bh2 * 32 + d)     * 112 + n2] = __float2half(c4[mi][ni][2] + b0);
                        g_vh[(bh2 * 32 + d + 1) * 112 + n2] = __float2half(c4[mi][ni][3] + b1);
                    } else {          // q,k: fp16x2 packed
                        float sc = (sel == 0) ? SCALE : 1.0f;
                        unsigned* basep = (sel == 0) ? g_qb : g_kb;
                        basep[(bh1 * NTOK + n)  * 16 + (d >> 1)] =
                            h2pack((c4[mi][ni][0] + b0) * sc, (c4[mi][ni][1] + b1) * sc);
                        basep[(bh2 * NTOK + n2) * 16 + (d >> 1)] =
                            h2pack((c4[mi][ni][2] + b0) * sc, (c4[mi][ni][3] + b1) * sc);
                    }
                }
            }
        }
    }
}

// ---------------- K2: fused attention, fp16 QK^T + fp16 PV (FA2 P-reuse) ----------------
#define KSU  20
#define VTU  60
#define SM_KU (NTOK * CSTR)
#define SM_VU (SM_KU + 104 * KSU)
#define ATTN_SMEM_BYTES ((SM_VU + 32 * VTU) * 4)
#define ATHREADS 224

__global__ void __launch_bounds__(ATHREADS, 3) k_attn() {
    extern __shared__ float sm[];
    float*    comb_s = sm;                                     // [98][108] fp32
    unsigned* k_su = reinterpret_cast<unsigned*>(sm + SM_KU);  // [104][20] f16x2
    unsigned* v_su = reinterpret_cast<unsigned*>(sm + SM_VU);  // [32][60]  f16x2 (V_t)

    const int t = blockIdx.x, h = blockIdx.y, w = blockIdx.z;
    const int tid = threadIdx.x, lane = tid & 31, warp = tid >> 5;
    const int g = lane >> 2, tg = lane & 3;
    const int r1 = warp * 16 + g, r2 = r1 + 8;
    const int cr1 = min(r1, NTOK - 1), cr2 = min(r2, NTOK - 1);
    const unsigned FULL = 0xffffffffu;
    const float L2E = 1.4426950408889634f;

    {
        const float* cg = g_comb + (size_t)(w * HEADS + h) * NTOK * CSTR;
        for (int i = tid; i < NTOK * CSTR; i += ATHREADS) comb_s[i] = cg[i];
    }
    for (int i = tid; i < 6 * KSU; i += ATHREADS) k_su[98 * KSU + i] = 0u;

    for (int jj = 0; jj < 8; jj++) {
        const int b = (t * 8 + jj) * NW + w;
        const size_t bh = (size_t)b * HEADS + h;
        const unsigned* gqb = g_qb + bh * NTOK * 16;
        const unsigned* gkb = g_kb + bh * NTOK * 16;
        const __half*   gvh = g_vh + bh * 32 * 112;

        __syncthreads();
        for (int i = tid; i < 392; i += ATHREADS) {     // K: 98 rows x 4 cp16
            int r = i >> 2, c = (i & 3) * 4;
            cp16(&k_su[r * KSU + c], &gkb[r * 16 + c]);
        }
        CP_COMMIT();
        for (int i = tid; i < 448; i += ATHREADS) {     // V_t: 32 rows x 14 cp16
            int r = i / 14, c = i - r * 14;
            cp16(&v_su[r * VTU + c * 4], &gvh[r * 112 + c * 8]);
        }
        CP_COMMIT();

        unsigned qu[2][4] = {{0u,0u,0u,0u},{0u,0u,0u,0u}};
        if (r1 < NTOK) {
            qu[0][0] = gqb[r1 * 16 + tg];     qu[0][2] = gqb[r1 * 16 + tg + 4];
            qu[1][0] = gqb[r1 * 16 + 8 + tg]; qu[1][2] = gqb[r1 * 16 + 8 + tg + 4];
        }
        if (r2 < NTOK) {
            qu[0][1] = gqb[r2 * 16 + tg];     qu[0][3] = gqb[r2 * 16 + tg + 4];
            qu[1][1] = gqb[r2 * 16 + 8 + tg]; qu[1][3] = gqb[r2 * 16 + 8 + tg + 4];
        }
        CP_WAIT1();
        __syncthreads();

        float s[13][4];
#pragma unroll
        for (int ni = 0; ni < 13; ni++)
            s[ni][0] = s[ni][1] = s[ni][2] = s[ni][3] = 0.f;
#pragma unroll
        for (int ch = 0; ch < 2; ch++) {
#pragma unroll
            for (int ni = 0; ni < 13; ni++) {
                unsigned b0 = k_su[(ni * 8 + g) * KSU + ch * 8 + tg];
                unsigned b1 = k_su[(ni * 8 + g) * KSU + ch * 8 + tg + 4];
                mma16h(s[ni], qu[ch][0], qu[ch][1], qu[ch][2], qu[ch][3], b0, b1);
            }
        }
        float m1 = -1e30f, m2 = -1e30f;
#pragma unroll
        for (int ni = 0; ni < 13; ni++) {
            int c0 = ni * 8 + tg * 2;
            float2 ca = *reinterpret_cast<const float2*>(&comb_s[cr1 * CSTR + c0]);
            float2 cb = *reinterpret_cast<const float2*>(&comb_s[cr2 * CSTR + c0]);
            s[ni][0] += ca.x; s[ni][1] += ca.y;
            s[ni][2] += cb.x; s[ni][3] += cb.y;
            m1 = fmaxf(m1, fmaxf(s[ni][0], s[ni][1]));
            m2 = fmaxf(m2, fmaxf(s[ni][2], s[ni][3]));
        }
        m1 = fmaxf(m1, __shfl_xor_sync(FULL, m1, 1));
        m1 = fmaxf(m1, __shfl_xor_sync(FULL, m1, 2));
        m2 = fmaxf(m2, __shfl_xor_sync(FULL, m2, 1));
        m2 = fmaxf(m2, __shfl_xor_sync(FULL, m2, 2));
        float sum1 = 0.f, sum2 = 0.f;
#pragma unroll
        for (int ni = 0; ni < 13; ni++) {
            s[ni][0] = ex2f((s[ni][0] - m1) * L2E);
            s[ni][1] = ex2f((s[ni][1] - m1) * L2E);
            s[ni][2] = ex2f((s[ni][2] - m2) * L2E);
            s[ni][3] = ex2f((s[ni][3] - m2) * L2E);
            sum1 += s[ni][0] + s[ni][1];
            sum2 += s[ni][2] + s[ni][3];
        }
        sum1 += __shfl_xor_sync(FULL, sum1, 1);
        sum1 += __shfl_xor_sync(FULL, sum1, 2);
        sum2 += __shfl_xor_sync(FULL, sum2, 1);
        sum2 += __shfl_xor_sync(FULL, sum2, 2);
        float inv1 = 1.0f / sum1, inv2 = 1.0f / sum2;

        CP_WAIT0();
        __syncthreads();

        float o[4][4];
#pragma unroll
        for (int ni = 0; ni < 4; ni++) o[ni][0] = o[ni][1] = o[ni][2] = o[ni][3] = 0.f;
#pragma unroll
        for (int kt = 0; kt < 7; kt++) {
            unsigned a0 = h2pack(s[2 * kt][0], s[2 * kt][1]);
            unsigned a1 = h2pack(s[2 * kt][2], s[2 * kt][3]);
            unsigned a2 = 0u, a3 = 0u;
            if (kt < 6) {
                a2 = h2pack(s[2 * kt + 1][0], s[2 * kt + 1][1]);
                a3 = h2pack(s[2 * kt + 1][2], s[2 * kt + 1][3]);
            }
#pragma unroll
            for (int ni = 0; ni < 4; ni++) {
                unsigned b0 = v_su[(ni * 8 + g) * VTU + 8 * kt + tg];
                unsigned b1 = v_su[(ni * 8 + g) * VTU + 8 * kt + tg + 4];
                mma16h(o[ni], a0, a1, a2, a3, b0, b1);
            }
        }
        float* gob = g_o + (size_t)b * NTOK * DIM + h * 32;
#pragma unroll
        for (int ni = 0; ni < 4; ni++) {
            int d = ni * 8 + tg * 2;
            if (r1 < NTOK)
                *reinterpret_cast<float2*>(&gob[r1 * DIM + d]) =
                    make_float2(tf32r(o[ni][0] * inv1), tf32r(o[ni][1] * inv1));
            if (r2 < NTOK)
                *reinterpret_cast<float2*>(&gob[r2 * DIM + d]) =
                    make_float2(tf32r(o[ni][2] * inv2), tf32r(o[ni][3] * inv2));
        }
    }
}

// ---------------- K3: output projection, 3-stage cp.async pipeline ----------------
#define PROJ_SMEM_BYTES (6 * 128 * 36 * 4)

__global__ void __launch_bounds__(256, 2) k_proj(const float* __restrict__ bias,
                                                 float* __restrict__ out) {
    extern __shared__ float smp[];
    float* Asb = smp;                   // 3 x [128][36]
    float* Bsb = smp + 3 * 128 * 36;    // 3 x [128][36]
    const int m0 = blockIdx.x * 128;
    const int tid = threadIdx.x, lane = tid & 31, warp = tid >> 5;
    const int g = lane >> 2, tg = lane & 3;
    const int wm = warp >> 2, wn = warp & 3;
    const int fi = (tid & 7) * 4, r0 = tid >> 3;

    auto prefetch = [&](int c, int buf) {
        const int kk = c * 32;
        float* ad = Asb + buf * (128 * 36);
        float* bd = Bsb + buf * (128 * 36);
#pragma unroll
        for (int rr = 0; rr < 4; rr++) {
            int r = r0 + rr * 32;
            cp16(&ad[r * 36 + fi], &g_o[(size_t)(m0 + r) * 128 + kk + fi]);
            cp16(&bd[r * 36 + fi], &g_proj_wr[(size_t)r * 128 + kk + fi]);
        }
    };
    prefetch(0, 0); CP_COMMIT();
    prefetch(1, 1); CP_COMMIT();

    float c4[4][4][4];
#pragma unroll
    for (int i = 0; i < 4; i++)
#pragma unroll
        for (int j = 0; j < 4; j++)
#pragma unroll
            for (int q = 0; q < 4; q++) c4[i][j][q] = 0.f;

    for (int c = 0; c < 4; c++) {
        const int buf = c % 3;
        const float* As = Asb + buf * (128 * 36);
        const float* Bs = Bsb + buf * (128 * 36);
        CP_WAIT1();
        __syncthreads();
        if (c + 2 < 4) { prefetch(c + 2, (c + 2) % 3); CP_COMMIT(); }
#pragma unroll
        for (int ks = 0; ks < 32; ks += 8) {
            float a[4][4], bb[4][2];
#pragma unroll
            for (int mi = 0; mi < 4; mi++) {
                int rr = wm * 64 + mi * 16 + g;
                a[mi][0] = As[rr * 36 + ks + tg];     a[mi][1] = As[(rr + 8) * 36 + ks + tg];
                a[mi][2] = As[rr * 36 + ks + tg + 4]; a[mi][3] = As[(rr + 8) * 36 + ks + tg + 4];
            }
#pragma unroll
            for (int ni = 0; ni < 4; ni++) {
                int cc = wn * 32 + ni * 8 + g;
                bb[ni][0] = Bs[cc * 36 + ks + tg]; bb[ni][1] = Bs[cc * 36 + ks + tg + 4];
            }
#pragma unroll
            for (int mi = 0; mi < 4; mi++)
#pragma unroll
                for (int ni = 0; ni < 4; ni++)
                    mma8(c4[mi][ni], a[mi][0], a[mi][1], a[mi][2], a[mi][3],
                         bb[ni][0], bb[ni][1]);
        }
        __syncthreads();
    }
#pragma unroll
    for (int ni = 0; ni < 4; ni++) {
        int col = wn * 32 + ni * 8 + tg * 2;
        float b0 = bias[col], b1 = bias[col + 1];
#pragma unroll
        for (int mi = 0; mi < 4; mi++) {
            int m = m0 + wm * 64 + mi * 16 + g;
            *reinterpret_cast<float2*>(&out[(size_t)m * 128 + col]) =
                make_float2(c4[mi][ni][0] + b0, c4[mi][ni][1] + b1);
            *reinterpret_cast<float2*>(&out[(size_t)(m + 8) * 128 + col]) =
                make_float2(c4[mi][ni][2] + b0, c4[mi][ni][3] + b1);
        }
    }
}

extern "C" void kernel_launch(void* const* d_in, const int* in_sizes, int n_in,
                              void* d_out, int out_size) {
    const float* x      = (const float*)d_in[0];
    const float* mask   = (const float*)d_in[1];
    const float* rpb    = (const float*)d_in[2];
    const float* qkv_w  = (const float*)d_in[3];
    const float* qkv_b  = (const float*)d_in[4];
    const float* proj_w = (const float*)d_in[5];
    const float* proj_b = (const float*)d_in[6];
    const int*   relidx = (const int*)d_in[7];
    float* out = (float*)d_out;

    cudaFuncSetAttribute(k_qkv,  cudaFuncAttributeMaxDynamicSharedMemorySize, QKV_SMEM_BYTES);
    cudaFuncSetAttribute(k_attn, cudaFuncAttributeMaxDynamicSharedMemorySize, ATTN_SMEM_BYTES);
    cudaFuncSetAttribute(k_proj, cudaFuncAttributeMaxDynamicSharedMemorySize, PROJ_SMEM_BYTES);

    k_prep<<<192, 256>>>(qkv_w, proj_w);
    k_comb<<<NW * HEADS, 256>>>(mask, rpb, relidx);
    k_qkv<<<BATCH * NTOK / 128, 256, QKV_SMEM_BYTES>>>(x, qkv_b);
    k_attn<<<dim3(8, HEADS, NW), ATHREADS, ATTN_SMEM_BYTES>>>();
    k_proj<<<BATCH * NTOK / 128, 256, PROJ_SMEM_BYTES>>>(proj_b, out);
}

// round 13
// speedup vs baseline: 1.1921x; 1.0159x over previous
#include <cuda_runtime.h>
#include <cuda_fp16.h>
#include <cstdint>
#include <cstddef>

#define NTOK   98
#define CSTR   108
#define HEADS  4
#define DIM    128
#define BATCH  4096
#define NW     64
#define SCALE  0.17677669529663687f

__device__ unsigned g_qb[(size_t)BATCH * HEADS * NTOK * 16];  // f16x2 packed, q*SCALE
__device__ unsigned g_kb[(size_t)BATCH * HEADS * NTOK * 16];  // f16x2 packed
__device__ __half   g_vh[(size_t)BATCH * HEADS * 32 * 112];   // V transposed [dim][tok], pads 0
__device__ float    g_o [(size_t)BATCH * NTOK * DIM];
__device__ float    g_comb[(size_t)NW * HEADS * NTOK * CSTR];
__device__ float    g_qkv_wr[384 * 128];                      // tf32-rounded (V rows used)
__device__ unsigned g_qkv_wh[256 * 64];                       // q,k weights fp16x2
__device__ float    g_proj_wr[128 * 128];

__device__ __forceinline__ float tf32r(float x) {
    unsigned u;
    asm("cvt.rna.tf32.f32 %0, %1;" : "=r"(u) : "f"(x));
    return __uint_as_float(u);
}
__device__ __forceinline__ float ex2f(float x) {
    float y;
    asm("ex2.approx.f32 %0, %1;" : "=f"(y) : "f"(x));
    return y;
}
__device__ __forceinline__ unsigned h2pack(float lo, float hi) {
    unsigned u;
    asm("cvt.rn.f16x2.f32 %0, %1, %2;" : "=r"(u) : "f"(hi), "f"(lo));
    return u;
}
__device__ __forceinline__ void mma8(float c[4], float a0, float a1, float a2, float a3,
                                     float b0, float b1) {
    asm volatile(
        "mma.sync.aligned.m16n8k8.row.col.f32.tf32.tf32.f32 "
        "{%0,%1,%2,%3},{%4,%5,%6,%7},{%8,%9},{%0,%1,%2,%3};\n"
        : "+f"(c[0]), "+f"(c[1]), "+f"(c[2]), "+f"(c[3])
        : "r"(__float_as_uint(a0)), "r"(__float_as_uint(a1)),
          "r"(__float_as_uint(a2)), "r"(__float_as_uint(a3)),
          "r"(__float_as_uint(b0)), "r"(__float_as_uint(b1)));
}
__device__ __forceinline__ void mma16h(float c[4], unsigned a0, unsigned a1,
                                       unsigned a2, unsigned a3,
                                       unsigned b0, unsigned b1) {
    asm volatile(
        "mma.sync.aligned.m16n8k16.row.col.f32.f16.f16.f32 "
        "{%0,%1,%2,%3},{%4,%5,%6,%7},{%8,%9},{%0,%1,%2,%3};\n"
        : "+f"(c[0]), "+f"(c[1]), "+f"(c[2]), "+f"(c[3])
        : "r"(a0), "r"(a1), "r"(a2), "r"(a3), "r"(b0), "r"(b1));
}
__device__ __forceinline__ void cp16(void* sptr, const void* gptr) {
    unsigned s = (unsigned)__cvta_generic_to_shared(sptr);
    asm volatile("cp.async.cg.shared.global [%0], [%1], 16;\n" :: "r"(s), "l"(gptr));
}
#define CP_COMMIT() asm volatile("cp.async.commit_group;\n" ::: "memory")
#define CP_WAIT0()  asm volatile("cp.async.wait_group 0;\n" ::: "memory")
#define CP_WAIT1()  asm volatile("cp.async.wait_group 1;\n" ::: "memory")
#define CP_WAIT2()  asm volatile("cp.async.wait_group 2;\n" ::: "memory")

// ---------------- K-1: pre-round weights (tf32 + fp16 for q,k rows) ----------------
__global__ void k_prep(const float* __restrict__ qkv_w, const float* __restrict__ proj_w) {
    int i = blockIdx.x * 256 + threadIdx.x;
    if (i < 384 * 128) g_qkv_wr[i] = tf32r(qkv_w[i]);
    if (i < 128 * 128) g_proj_wr[i] = tf32r(proj_w[i]);
    if (i < 256 * 64) {
        int r = i >> 6, j = i & 63;
        g_qkv_wh[i] = h2pack(qkv_w[r * 128 + 2 * j], qkv_w[r * 128 + 2 * j + 1]);
    }
}

// ---------------- K0: comb = mask + gathered bias, padded ----------------
__global__ void k_comb(const float* __restrict__ mask,
                       const float* __restrict__ rpb,
                       const int* __restrict__ relidx) {
    const int w = blockIdx.x >> 2, h = blockIdx.x & 3;
    float* dst = g_comb + (size_t)(w * HEADS + h) * NTOK * CSTR;
    const float* msk = mask + (size_t)w * NTOK * NTOK;
    for (int idx = threadIdx.x; idx < NTOK * CSTR; idx += blockDim.x) {
        int i = idx / CSTR, j = idx - i * CSTR;
        float v = -10000.0f;
        if (j < NTOK) v = msk[i * NTOK + j] + rpb[relidx[i * NTOK + j] * HEADS + h];
        dst[idx] = v;
    }
}

// ---------------- K1: merged QKV — 8 chunks: Q,K fp16 (64-dim), V tf32 (32-dim) ------
#define QKV_SMEM_BYTES ((128 * 132 + 2 * 128 * 36) * 4)

__global__ void __launch_bounds__(256, 2) k_qkv(const float* __restrict__ x,
                                                const float* __restrict__ bias) {
    extern __shared__ float smq[];
    float (*As)[132] = reinterpret_cast<float(*)[132]>(smq);   // fp32 x tile, whole kernel
    float* Bsbuf = smq + 128 * 132;                             // 2 x 18432B chunk buffers
    const int m0 = blockIdx.x * 128;
    const int tid = threadIdx.x, lane = tid & 31, warp = tid >> 5;
    const int g = lane >> 2, tg = lane & 3;
    const int wm = warp >> 2, wn = warp & 3;
    const int fi = (tid & 7) * 4, r0 = tid >> 3;

    {   // load full 128x128 x tile once (rna-rounded)
        const int c = (tid & 31) * 4, rb = tid >> 5;
#pragma unroll
        for (int rr = 0; rr < 16; rr++) {
            int r = rb + rr * 8;
            float4 v4 = *reinterpret_cast<const float4*>(&x[(size_t)(m0 + r) * 128 + c]);
            *reinterpret_cast<float4*>(&As[r][c]) =
                make_float4(tf32r(v4.x), tf32r(v4.y), tf32r(v4.z), tf32r(v4.w));
        }
    }

    // chunk c: 0,1 = Q fp16 halves; 2,3 = K fp16 halves; 4..7 = V tf32 32-dim
    auto prefetch = [&](int c, int buf) {
        if (c < 4) {    // fp16 weights: 128 rows x 32 u32, smem stride 36 u32
            const unsigned* src = g_qkv_wh + (size_t)((c >> 1) * 128) * 64 + (c & 1) * 32;
            unsigned* dst = reinterpret_cast<unsigned*>(Bsbuf + buf * (128 * 36));
#pragma unroll
            for (int ii = 0; ii < 4; ii++) {
                int i = tid + ii * 256;           // 0..1023
                int r = i >> 3, q4 = (i & 7) * 4;
                cp16(&dst[r * 36 + q4], &src[(size_t)r * 64 + q4]);
            }
        } else {        // fp32 V weights: 128 rows x 32 floats, stride 36
            const float* src = g_qkv_wr + (size_t)256 * 128 + (c - 4) * 32;
            float* dst = Bsbuf + buf * (128 * 36);
#pragma unroll
            for (int rr = 0; rr < 4; rr++) {
                int r = r0 + rr * 32;
                cp16(&dst[r * 36 + fi], &src[(size_t)r * 128 + fi]);
            }
        }
    };
    prefetch(0, 0);
    CP_COMMIT();

    float c4[4][4][4];
    for (int c = 0; c < 8; c++) {
        if (c == 0 || c == 2 || c == 4) {
#pragma unroll
            for (int i = 0; i < 4; i++)
#pragma unroll
                for (int j = 0; j < 4; j++)
#pragma unroll
                    for (int q = 0; q < 4; q++) c4[i][j][q] = 0.f;
        }
        CP_WAIT0();
        __syncthreads();
        if (c + 1 < 8) { prefetch(c + 1, (c + 1) & 1); CP_COMMIT(); }

        if (c < 4) {    // fp16 64-dim chunk = 4 x m16n8k16
            const unsigned* Bh = reinterpret_cast<const unsigned*>(Bsbuf + (c & 1) * (128 * 36));
            const int dim0 = (c & 1) * 64;
#pragma unroll
            for (int ks = 0; ks < 4; ks++) {
                const int base = dim0 + ks * 16;
                unsigned a[4][4], bb[4][2];
#pragma unroll
                for (int mi = 0; mi < 4; mi++) {
                    int rr = wm * 64 + mi * 16 + g;
                    float2 lo1 = *reinterpret_cast<const float2*>(&As[rr][base + 2 * tg]);
                    float2 lo2 = *reinterpret_cast<const float2*>(&As[rr + 8][base + 2 * tg]);
                    float2 hi1 = *reinterpret_cast<const float2*>(&As[rr][base + 8 + 2 * tg]);
                    float2 hi2 = *reinterpret_cast<const float2*>(&As[rr + 8][base + 8 + 2 * tg]);
                    a[mi][0] = h2pack(lo1.x, lo1.y);
                    a[mi][1] = h2pack(lo2.x, lo2.y);
                    a[mi][2] = h2pack(hi1.x, hi1.y);
                    a[mi][3] = h2pack(hi2.x, hi2.y);
                }
#pragma unroll
                for (int ni = 0; ni < 4; ni++) {
                    int cc = wn * 32 + ni * 8 + g;
                    bb[ni][0] = Bh[cc * 36 + ks * 8 + tg];
                    bb[ni][1] = Bh[cc * 36 + ks * 8 + tg + 4];
                }
#pragma unroll
                for (int mi = 0; mi < 4; mi++)
#pragma unroll
                    for (int ni = 0; ni < 4; ni++)
                        mma16h(c4[mi][ni], a[mi][0], a[mi][1], a[mi][2], a[mi][3],
                               bb[ni][0], bb[ni][1]);
            }
        } else {        // tf32 32-dim chunk = 4 x m16n8k8 (V)
            const float* Bs = Bsbuf + (c & 1) * (128 * 36);
            const int kk = (c - 4) * 32;
#pragma unroll
            for (int ks = 0; ks < 32; ks += 8) {
                float a[4][4], bb[4][2];
#pragma unroll
                for (int mi = 0; mi < 4; mi++) {
                    int rr = wm * 64 + mi * 16 + g;
                    a[mi][0] = As[rr][kk + ks + tg];     a[mi][1] = As[rr + 8][kk + ks + tg];
                    a[mi][2] = As[rr][kk + ks + tg + 4]; a[mi][3] = As[rr + 8][kk + ks + tg + 4];
                }
#pragma unroll
                for (int ni = 0; ni < 4; ni++) {
                    int cc = wn * 32 + ni * 8 + g;
                    bb[ni][0] = Bs[cc * 36 + ks + tg]; bb[ni][1] = Bs[cc * 36 + ks + tg + 4];
                }
#pragma unroll
                for (int mi = 0; mi < 4; mi++)
#pragma unroll
                    for (int ni = 0; ni < 4; ni++)
                        mma8(c4[mi][ni], a[mi][0], a[mi][1], a[mi][2], a[mi][3],
                             bb[ni][0], bb[ni][1]);
            }
        }
        __syncthreads();

        if (c == 1 || c == 3 || c == 7) {   // epilogue: Q, K, or V
            int sel = (c == 1) ? 0 : ((c == 3) ? 1 : 2);
#pragma unroll
            for (int ni = 0; ni < 4; ni++) {
                int col = sel * 128 + wn * 32 + ni * 8 + tg * 2;
                float b0 = bias[col], b1 = bias[col + 1];
                int o = col & 127, h = o >> 5, d = o & 31;
#pragma unroll
                for (int mi = 0; mi < 4; mi++) {
                    int m = m0 + wm * 64 + mi * 16 + g;
                    int b = m / NTOK, n = m - b * NTOK;
                    int m2 = m + 8, b2 = m2 / NTOK, n2 = m2 - b2 * NTOK;
                    size_t bh1 = (size_t)b * HEADS + h;
                    size_t bh2 = (size_t)b2 * HEADS + h;
                    if (sel == 2) {   // V: fp16 transposed [dim][112 tok]
                        g_vh[(bh1 * 32 + d)     * 112 + n]  = __float2half(c4[mi][ni][0] + b0);
                        g_vh[(bh1 * 32 + d + 1) * 112 + n]  = __float2half(c4[mi][ni][1] + b1);
                        g_vh[(bh2 * 32 + d)     * 112 + n2] = __float2half(c4[mi][ni][2] + b0);
                        g_vh[(bh2 * 32 + d + 1) * 112 + n2] = __float2half(c4[mi][ni][3] + b1);
                    } else {          // q,k: fp16x2 packed
                        float sc = (sel == 0) ? SCALE : 1.0f;
                        unsigned* basep = (sel == 0) ? g_qb : g_kb;
                        basep[(bh1 * NTOK + n)  * 16 + (d >> 1)] =
                            h2pack((c4[mi][ni][0] + b0) * sc, (c4[mi][ni][1] + b1) * sc);
                        basep[(bh2 * NTOK + n2) * 16 + (d >> 1)] =
                            h2pack((c4[mi][ni][2] + b0) * sc, (c4[mi][ni][3] + b1) * sc);
                    }
                }
            }
        }
    }
}

// ---------------- K2: fused attention, double-buffered K/V, fp16 QK^T + fp16 PV ------
#define KSU  20
#define VTU  60
#define KBUFU (104 * KSU)
#define VBUFU (32 * VTU)
#define SM_KU (NTOK * CSTR)
#define SM_VU (SM_KU + 2 * KBUFU)
#define ATTN_SMEM_BYTES ((SM_VU + 2 * VBUFU) * 4)
#define ATHREADS 224

__global__ void __launch_bounds__(ATHREADS, 3) k_attn() {
    extern __shared__ float sm[];
    float*    comb_s = sm;                                     // [98][108] fp32
    unsigned* k_su = reinterpret_cast<unsigned*>(sm + SM_KU);  // 2 x [104][20] f16x2
    unsigned* v_su = reinterpret_cast<unsigned*>(sm + SM_VU);  // 2 x [32][60]  f16x2 (V_t)

    const int t = blockIdx.x, h = blockIdx.y, w = blockIdx.z;
    const int tid = threadIdx.x, lane = tid & 31, warp = tid >> 5;
    const int g = lane >> 2, tg = lane & 3;
    const int r1 = warp * 16 + g, r2 = r1 + 8;
    const int cr1 = min(r1, NTOK - 1), cr2 = min(r2, NTOK - 1);
    const unsigned FULL = 0xffffffffu;
    const float L2E = 1.4426950408889634f;

    {
        const float* cg = g_comb + (size_t)(w * HEADS + h) * NTOK * CSTR;
        for (int i = tid; i < NTOK * CSTR; i += ATHREADS) comb_s[i] = cg[i];
    }
    // zero K pad rows 98..103 in both buffers
    for (int i = tid; i < 6 * KSU; i += ATHREADS) {
        k_su[98 * KSU + i] = 0u;
        k_su[KBUFU + 98 * KSU + i] = 0u;
    }

    auto prefetch = [&](int jj, int buf) {
        const int b = (t * 8 + jj) * NW + w;
        const size_t bh = (size_t)b * HEADS + h;
        const unsigned* gkb = g_kb + bh * NTOK * 16;
        const __half*   gvh = g_vh + bh * 32 * 112;
        unsigned* kd = k_su + buf * KBUFU;
        unsigned* vd = v_su + buf * VBUFU;
        for (int i = tid; i < 392; i += ATHREADS) {     // K: 98 rows x 4 cp16
            int r = i >> 2, c = (i & 3) * 4;
            cp16(&kd[r * KSU + c], &gkb[r * 16 + c]);
        }
        CP_COMMIT();
        for (int i = tid; i < 448; i += ATHREADS) {     // V_t: 32 rows x 14 cp16
            int r = i / 14, c = i - r * 14;
            cp16(&vd[r * VTU + c * 4], &gvh[r * 112 + c * 8]);
        }
        CP_COMMIT();
    };
    prefetch(0, 0);

    for (int jj = 0; jj < 8; jj++) {
        const int cur = jj & 1;
        const int b = (t * 8 + jj) * NW + w;
        const size_t bh = (size_t)b * HEADS + h;
        const unsigned* gqb = g_qb + bh * NTOK * 16;
        const unsigned* kb = k_su + cur * KBUFU;
        const unsigned* vb = v_su + cur * VBUFU;

        // q fragments (packed f16x2, pre-scaled) — overlaps the K wait
        unsigned qu[2][4] = {{0u,0u,0u,0u},{0u,0u,0u,0u}};
        if (r1 < NTOK) {
            qu[0][0] = gqb[r1 * 16 + tg];     qu[0][2] = gqb[r1 * 16 + tg + 4];
            qu[1][0] = gqb[r1 * 16 + 8 + tg]; qu[1][2] = gqb[r1 * 16 + 8 + tg + 4];
        }
        if (r2 < NTOK) {
            qu[0][1] = gqb[r2 * 16 + tg];     qu[0][3] = gqb[r2 * 16 + tg + 4];
            qu[1][1] = gqb[r2 * 16 + 8 + tg]; qu[1][3] = gqb[r2 * 16 + 8 + tg + 4];
        }
        CP_WAIT1();                 // K[cur] landed (V[cur] may still be in flight)
        __syncthreads();            // also proves all warps done reading buffer cur^1
        if (jj < 7) prefetch(jj + 1, cur ^ 1);   // overlaps S + softmax + PV

        // S = q @ k^T (f16 m16n8k16, 2 dim-chunks)
        float s[13][4];
#pragma unroll
        for (int ni = 0; ni < 13; ni++)
            s[ni][0] = s[ni][1] = s[ni][2] = s[ni][3] = 0.f;
#pragma unroll
        for (int ch = 0; ch < 2; ch++) {
#pragma unroll
            for (int ni = 0; ni < 13; ni++) {
                unsigned b0 = kb[(ni * 8 + g) * KSU + ch * 8 + tg];
                unsigned b1 = kb[(ni * 8 + g) * KSU + ch * 8 + tg + 4];
                mma16h(s[ni], qu[ch][0], qu[ch][1], qu[ch][2], qu[ch][3], b0, b1);
            }
        }
        // bias (float2) + quad softmax
        float m1 = -1e30f, m2 = -1e30f;
#pragma unroll
        for (int ni = 0; ni < 13; ni++) {
            int c0 = ni * 8 + tg * 2;
            float2 ca = *reinterpret_cast<const float2*>(&comb_s[cr1 * CSTR + c0]);
            float2 cb = *reinterpret_cast<const float2*>(&comb_s[cr2 * CSTR + c0]);
            s[ni][0] += ca.x; s[ni][1] += ca.y;
            s[ni][2] += cb.x; s[ni][3] += cb.y;
            m1 = fmaxf(m1, fmaxf(s[ni][0], s[ni][1]));
            m2 = fmaxf(m2, fmaxf(s[ni][2], s[ni][3]));
        }
        m1 = fmaxf(m1, __shfl_xor_sync(FULL, m1, 1));
        m1 = fmaxf(m1, __shfl_xor_sync(FULL, m1, 2));
        m2 = fmaxf(m2, __shfl_xor_sync(FULL, m2, 1));
        m2 = fmaxf(m2, __shfl_xor_sync(FULL, m2, 2));
        float sum1 = 0.f, sum2 = 0.f;
#pragma unroll
        for (int ni = 0; ni < 13; ni++) {
            s[ni][0] = ex2f((s[ni][0] - m1) * L2E);
            s[ni][1] = ex2f((s[ni][1] - m1) * L2E);
            s[ni][2] = ex2f((s[ni][2] - m2) * L2E);
            s[ni][3] = ex2f((s[ni][3] - m2) * L2E);
            sum1 += s[ni][0] + s[ni][1];
            sum2 += s[ni][2] + s[ni][3];
        }
        sum1 += __shfl_xor_sync(FULL, sum1, 1);
        sum1 += __shfl_xor_sync(FULL, sum1, 2);
        sum2 += __shfl_xor_sync(FULL, sum2, 1);
        sum2 += __shfl_xor_sync(FULL, sum2, 2);
        float inv1 = 1.0f / sum1, inv2 = 1.0f / sum2;

        if (jj < 7) { CP_WAIT2(); }   // V[cur] done; K[next],V[next] still flying
        else        { CP_WAIT0(); }   // last iter: only V[cur] outstanding
        __syncthreads();

        // O = P @ V : P accumulators repacked as f16 A-fragments (no shfl)
        float o[4][4];
#pragma unroll
        for (int ni = 0; ni < 4; ni++) o[ni][0] = o[ni][1] = o[ni][2] = o[ni][3] = 0.f;
#pragma unroll
        for (int kt = 0; kt < 7; kt++) {
            unsigned a0 = h2pack(s[2 * kt][0], s[2 * kt][1]);
            unsigned a1 = h2pack(s[2 * kt][2], s[2 * kt][3]);
            unsigned a2 = 0u, a3 = 0u;
            if (kt < 6) {
                a2 = h2pack(s[2 * kt + 1][0], s[2 * kt + 1][1]);
                a3 = h2pack(s[2 * kt + 1][2], s[2 * kt + 1][3]);
            }
#pragma unroll
            for (int ni = 0; ni < 4; ni++) {
                unsigned b0 = vb[(ni * 8 + g) * VTU + 8 * kt + tg];
                unsigned b1 = vb[(ni * 8 + g) * VTU + 8 * kt + tg + 4];
                mma16h(o[ni], a0, a1, a2, a3, b0, b1);
            }
        }
        float* gob = g_o + (size_t)b * NTOK * DIM + h * 32;
#pragma unroll
        for (int ni = 0; ni < 4; ni++) {
            int d = ni * 8 + tg * 2;
            if (r1 < NTOK)
                *reinterpret_cast<float2*>(&gob[r1 * DIM + d]) =
                    make_float2(tf32r(o[ni][0] * inv1), tf32r(o[ni][1] * inv1));
            if (r2 < NTOK)
                *reinterpret_cast<float2*>(&gob[r2 * DIM + d]) =
                    make_float2(tf32r(o[ni][2] * inv2), tf32r(o[ni][3] * inv2));
        }
    }
}

// ---------------- K3: output projection, 3-stage cp.async pipeline ----------------
#define PROJ_SMEM_BYTES (6 * 128 * 36 * 4)

__global__ void __launch_bounds__(256, 2) k_proj(const float* __restrict__ bias,
                                                 float* __restrict__ out) {
    extern __shared__ float smp[];
    float* Asb = smp;                   // 3 x [128][36]
    float* Bsb = smp + 3 * 128 * 36;    // 3 x [128][36]
    const int m0 = blockIdx.x * 128;
    const int tid = threadIdx.x, lane = tid & 31, warp = tid >> 5;
    const int g = lane >> 2, tg = lane & 3;
    const int wm = warp >> 2, wn = warp & 3;
    const int fi = (tid & 7) * 4, r0 = tid >> 3;

    auto prefetch = [&](int c, int buf) {
        const int kk = c * 32;
        float* ad = Asb + buf * (128 * 36);
        float* bd = Bsb + buf * (128 * 36);
#pragma unroll
        for (int rr = 0; rr < 4; rr++) {
            int r = r0 + rr * 32;
            cp16(&ad[r * 36 + fi], &g_o[(size_t)(m0 + r) * 128 + kk + fi]);
            cp16(&bd[r * 36 + fi], &g_proj_wr[(size_t)r * 128 + kk + fi]);
        }
    };
    prefetch(0, 0); CP_COMMIT();
    prefetch(1, 1); CP_COMMIT();

    float c4[4][4][4];
#pragma unroll
    for (int i = 0; i < 4; i++)
#pragma unroll
        for (int j = 0; j < 4; j++)
#pragma unroll
            for (int q = 0; q < 4; q++) c4[i][j][q] = 0.f;

    for (int c = 0; c < 4; c++) {
        const int buf = c % 3;
        const float* As = Asb + buf * (128 * 36);
        const float* Bs = Bsb + buf * (128 * 36);
        CP_WAIT1();
        __syncthreads();
        if (c + 2 < 4) { prefetch(c + 2, (c + 2) % 3); CP_COMMIT(); }
#pragma unroll
        for (int ks = 0; ks < 32; ks += 8) {
            float a[4][4], bb[4][2];
#pragma unroll
            for (int mi = 0; mi < 4; mi++) {
                int rr = wm * 64 + mi * 16 + g;
                a[mi][0] = As[rr * 36 + ks + tg];     a[mi][1] = As[(rr + 8) * 36 + ks + tg];
                a[mi][2] = As[rr * 36 + ks + tg + 4]; a[mi][3] = As[(rr + 8) * 36 + ks + tg + 4];
            }
#pragma unroll
            for (int ni = 0; ni < 4; ni++) {
                int cc = wn * 32 + ni * 8 + g;
                bb[ni][0] = Bs[cc * 36 + ks + tg]; bb[ni][1] = Bs[cc * 36 + ks + tg + 4];
            }
#pragma unroll
            for (int mi = 0; mi < 4; mi++)
#pragma unroll
                for (int ni = 0; ni < 4; ni++)
                    mma8(c4[mi][ni], a[mi][0], a[mi][1], a[mi][2], a[mi][3],
                         bb[ni][0], bb[ni][1]);
        }
        __syncthreads();
    }
#pragma unroll
    for (int ni = 0; ni < 4; ni++) {
        int col = wn * 32 + ni * 8 + tg * 2;
        float b0 = bias[col], b1 = bias[col + 1];
#pragma unroll
        for (int mi = 0; mi < 4; mi++) {
            int m = m0 + wm * 64 + mi * 16 + g;
            *reinterpret_cast<float2*>(&out[(size_t)m * 128 + col]) =
                make_float2(c4[mi][ni][0] + b0, c4[mi][ni][1] + b1);
            *reinterpret_cast<float2*>(&out[(size_t)(m + 8) * 128 + col]) =
                make_float2(c4[mi][ni][2] + b0, c4[mi][ni][3] + b1);
        }
    }
}

extern "C" void kernel_launch(void* const* d_in, const int* in_sizes, int n_in,
                              void* d_out, int out_size) {
    const float* x      = (const float*)d_in[0];
    const float* mask   = (const float*)d_in[1];
    const float* rpb    = (const float*)d_in[2];
    const float* qkv_w  = (const float*)d_in[3];
    const float* qkv_b  = (const float*)d_in[4];
    const float* proj_w = (const float*)d_in[5];
    const float* proj_b = (const float*)d_in[6];
    const int*   relidx = (const int*)d_in[7];
    float* out = (float*)d_out;

    cudaFuncSetAttribute(k_qkv,  cudaFuncAttributeMaxDynamicSharedMemorySize, QKV_SMEM_BYTES);
    cudaFuncSetAttribute(k_attn, cudaFuncAttributeMaxDynamicSharedMemorySize, ATTN_SMEM_BYTES);
    cudaFuncSetAttribute(k_proj, cudaFuncAttributeMaxDynamicSharedMemorySize, PROJ_SMEM_BYTES);

    k_prep<<<192, 256>>>(qkv_w, proj_w);
    k_comb<<<NW * HEADS, 256>>>(mask, rpb, relidx);
    k_qkv<<<BATCH * NTOK / 128, 256, QKV_SMEM_BYTES>>>(x, qkv_b);
    k_attn<<<dim3(8, HEADS, NW), ATHREADS, ATTN_SMEM_BYTES>>>();
    k_proj<<<BATCH * NTOK / 128, 256, PROJ_SMEM_BYTES>>>(proj_b, out);
}